// round 8
// baseline (speedup 1.0000x reference)
#include <cuda_runtime.h>
#include <cstdint>

// Shapes: re, gt are (B=32, C=10, H=192, W=320) float32, contiguous.
#define NB     32
#define NC     10
#define HW4    15360                  // (192*320)/4 float4 groups per channel
#define TILE   128                    // float4 groups per block
#define BPB    (HW4/TILE)             // 120 blocks per batch image
#define GRID   (NB*BPB)               // 3840 blocks
#define BLK    128
#define NACC   6
#define EPSF   6e-8f

// [0]=nv [1]=num_pos [2]=focal_sum
// [3]=A (pos+height+const) [4]=B (len1+trig1) [5]=C (len2+trig2)
__device__ float g_part[NACC][GRID];
__device__ unsigned int g_count = 0;   // reset by last block each launch

__device__ __forceinline__ float sl1(float d) {
    float ad = fabsf(d);
    return ad < 1.0f ? 0.5f * d * d : ad - 0.5f;
}

__device__ __forceinline__ float c4(const float4& v, int j) {
    return j == 0 ? v.x : (j == 1 ? v.y : (j == 2 ? v.z : v.w));
}

__device__ __forceinline__ void cp16(uint32_t dst, const float4* src) {
    asm volatile("cp.async.cg.shared.global [%0], [%1], 16;"
                 :: "r"(dst), "l"(src));
}

__global__ void __launch_bounds__(BLK, 5)
loss_kernel(const float* __restrict__ re, const float* __restrict__ gt,
            float* __restrict__ out) {
    // 20 streams x TILE float4 = 40 KB. Stream s: ch for gt (s=ch),
    // 10+ch for re.
    __shared__ float4 tile[20][TILE];

    const int tid = threadIdx.x;
    const int blk = blockIdx.x;
    const int b   = blk / BPB;
    const int g0  = (blk - b * BPB) * TILE;

    const float4* gp = (const float4*)gt + (size_t)b * (NC * HW4) + g0 + tid;
    const float4* rp = (const float4*)re + (size_t)b * (NC * HW4) + g0 + tid;

    const uint32_t sa = (uint32_t)__cvta_generic_to_shared(&tile[0][tid]);

    // Group A: channel 0 (mask + focal inputs)
    cp16(sa + 0 * (TILE * 16), gp);
    cp16(sa + 10 * (TILE * 16), rp);
    asm volatile("cp.async.commit_group;");
    // Group B: channels 1..9
#pragma unroll
    for (int ch = 1; ch < NC; ch++) {
        cp16(sa + ch * (TILE * 16), gp + ch * HW4);
        cp16(sa + (10 + ch) * (TILE * 16), rp + ch * HW4);
    }
    asm volatile("cp.async.commit_group;");

    float a_nv = 0.f, a_np = 0.f, a_f = 0.f, a_A = 0.f, a_B = 0.f, a_C = 0.f;

    // Wait for channel 0 only; compute focal while ch1-9 still in flight.
    asm volatile("cp.async.wait_group 1;");
    const float4 G0 = tile[0][tid];
    const float4 R0 = tile[10][tid];

    float mvf[4];
#pragma unroll
    for (int j = 0; j < 4; j++) {
        const float g = c4(G0, j);
        const float r = c4(R0, j);
        const bool  m0  = (g >= 0.0f);
        const bool  pos = (g >= 0.1f);              // FOCAL_THR, implies m0
        const float safe = fminf(fmaxf(r, 1e-6f), 1.0f - 1e-6f);
        const float larg = pos ? (safe + EPSF) : (1.0f + EPSF - safe);
        const float lg   = __logf(larg);            // larg > 0 always
        const float d0   = g - r;
        const float om   = 1.0f - g;
        const float om2  = om * om;
        float w = pos ? (d0 * d0) : (r * r * (om2 * om2));
        if (!m0) w = 0.0f;
        a_f -= w * lg;
        if (pos) a_np += 1.0f;
        mvf[j] = (g == 1.0f) ? 1.0f : 0.0f;
        a_nv += mvf[j];
    }

    asm volatile("cp.async.wait_group 0;");

    // Channel-major compute: small live register set per stage.
    {   // pos: channels 1,2 (0.5 = POS_W/2)
        const float4 R1 = tile[11][tid], G1 = tile[1][tid];
        const float4 R2 = tile[12][tid], G2 = tile[2][tid];
#pragma unroll
        for (int j = 0; j < 4; j++)
            a_A += mvf[j] * 0.5f * (sl1(c4(R1,j) - c4(G1,j))
                                  + sl1(c4(R2,j) - c4(G2,j)));
    }
    {   // height: channel 9 (0.1 = LEN_W)
        const float4 R9 = tile[19][tid], G9 = tile[9][tid];
#pragma unroll
        for (int j = 0; j < 4; j++)
            a_A += mvf[j] * 0.1f * sl1(c4(R9,j) - c4(G9,j));
    }
    {   // length straight/crossed: channels 3,6 (0.05 = LEN_W/2)
        const float4 R3 = tile[13][tid], G3 = tile[3][tid];
        const float4 R6 = tile[16][tid], G6 = tile[6][tid];
#pragma unroll
        for (int j = 0; j < 4; j++) {
            const float r3 = c4(R3,j), g3 = c4(G3,j);
            const float r6 = c4(R6,j), g6 = c4(G6,j);
            a_B += mvf[j] * 0.05f * (sl1(r3 - g3) + sl1(r6 - g6));
            a_C += mvf[j] * 0.05f * (sl1(r3 - g6) + sl1(r6 - g3));
        }
    }
    {   // trig + const: channels 4,5,7,8
        const float4 R4 = tile[14][tid], G4 = tile[4][tid];
        const float4 R5 = tile[15][tid], G5 = tile[5][tid];
        const float4 R7 = tile[17][tid], G7 = tile[7][tid];
        const float4 R8 = tile[18][tid], G8 = tile[8][tid];
#pragma unroll
        for (int j = 0; j < 4; j++) {
            const float r4 = c4(R4,j), g4 = c4(G4,j);
            const float r5 = c4(R5,j), g5 = c4(G5,j);
            const float r7 = c4(R7,j), g7 = c4(G7,j);
            const float r8 = c4(R8,j), g8 = c4(G8,j);
            const float d44 = r4 - g4, d77 = r7 - g7;
            const float d55 = r5 - g5, d88 = r8 - g8;
            a_B += mvf[j] * 0.5f * (d44*d44 + d77*d77 + d55*d55 + d88*d88);
            const float d47 = r4 - g7, d74 = r7 - g4;
            const float d58 = r5 - g8, d85 = r8 - g5;
            a_C += mvf[j] * 0.5f * (d47*d47 + d74*d74 + d58*d58 + d85*d85);
            const float c1 = 1.0f - r5*r5 - r4*r4;
            const float c2 = 1.0f - r8*r8 - r7*r7;
            a_A += mvf[j] * 0.5f * (c1*c1 + c2*c2);
        }
    }

    // Block reduction: warp shuffle -> shared -> per-block partial slot.
    float acc[NACC] = {a_nv, a_np, a_f, a_A, a_B, a_C};
    __shared__ float sh[BLK/32][NACC];
    const int lane = tid & 31;
    const int warp = tid >> 5;
#pragma unroll
    for (int k = 0; k < NACC; k++) {
        float v = acc[k];
#pragma unroll
        for (int o = 16; o > 0; o >>= 1)
            v += __shfl_down_sync(0xffffffffu, v, o);
        if (lane == 0) sh[warp][k] = v;
    }
    __syncthreads();
    if (tid < NACC) {
        float v = 0.0f;
#pragma unroll
        for (int w = 0; w < BLK/32; w++) v += sh[w][tid];
        g_part[tid][blk] = v;
    }

    // Last-block-done: the final block to arrive reduces all partials.
    __shared__ bool is_last;
    __threadfence();
    __syncthreads();
    if (tid == 0) {
        unsigned int old = atomicAdd(&g_count, 1u);
        is_last = (old == GRID - 1);
    }
    __syncthreads();
    if (!is_last) return;

    __threadfence();   // ensure we see every block's partials

    // 4 warps reduce 6 accumulators: warp w -> k=w; warps 0,1 also k=w+4.
    __shared__ float tot[NACC];
#pragma unroll
    for (int pass = 0; pass < 2; pass++) {
        const int k = warp + pass * 4;
        if (k < NACC) {
            float v = 0.0f;
            for (int j = lane; j < GRID; j += 32) v += g_part[k][j];
#pragma unroll
            for (int o = 16; o > 0; o >>= 1)
                v += __shfl_down_sync(0xffffffffu, v, o);
            if (lane == 0) tot[k] = v;
        }
    }
    __syncthreads();

    if (tid == 0) {
        g_count = 0;   // reset for next graph replay

        const float nv      = tot[0];
        const float num_pos = tot[1];
        const float S       = tot[2];
        const float focal = (num_pos == 0.0f) ? S : S / num_pos;
        out[0] = focal + (tot[3] + fminf(tot[4], tot[5])) / nv;
    }
}

extern "C" void kernel_launch(void* const* d_in, const int* in_sizes, int n_in,
                              void* d_out, int out_size) {
    const float* re = (const float*)d_in[0];
    const float* gt = (const float*)d_in[1];
    float* out = (float*)d_out;

    loss_kernel<<<GRID, BLK>>>(re, gt, out);
}